// round 6
// baseline (speedup 1.0000x reference)
#include <cuda_runtime.h>
#include <cstddef>
#include <cstdint>

// Bidirectional 2-layer LSTM; only batch row 255 feeds the output (B -> 1).
// Round 6: 8-CTA cluster engines with DSMEM h-broadcast + hardware mbarriers.
//   - 4 engines (L0fw, L0bw, L1fw, L1bw), 8 CTAs x 256 threads each, 128 z-cols/CTA
//   - gate warp stores h to all peers' SMEM + arrives on all peers' mbarriers
//   - helpers (16/dir) compute zx1 = h0 @ W1[0:256] + b1 via PROVEN counter sync
//   - fetch warp prefetches zx into SMEM during gate phase (off critical path)

#define TT 512
#define HD 256
#define DD 128
#define BLAST 255

// ---------------- scratch (static device memory) ----------------------------
__device__ float g_zx0[2][TT][1024];   // layer0 x-part + bias (phaseA)
__device__ float g_zx1[2][TT][1024];   // layer1 x-part + bias (helpers)
__device__ float g_h0[2][TT][HD];      // layer0 h (published for helpers)
__device__ float g_h1[2][TT][HD];      // layer1 h (for phaseC)
__device__ unsigned g_cnt0[2];         // L0 production counters (per dir)
__device__ unsigned g_cntzx[2];        // helper zx1 counters (per dir)

// fast saturating gate math (proven R5)
__device__ __forceinline__ float fsig(float x) {
    return __fdividef(1.0f, 1.0f + __expf(-x));
}
__device__ __forceinline__ float ftanh(float x) {
    return 1.0f - __fdividef(2.0f, __expf(2.0f * x) + 1.0f);
}

// proven counter ops (R2/R5)
__device__ __forceinline__ void rel_add(unsigned* p) {
    asm volatile("red.release.gpu.global.add.u32 [%0], 1;" :: "l"(p) : "memory");
}
__device__ __forceinline__ unsigned acq_ld(const unsigned* p) {
    unsigned v;
    asm volatile("ld.acquire.gpu.global.u32 %0, [%1];" : "=r"(v) : "l"(p) : "memory");
    return v;
}

// cluster / mbarrier primitives
__device__ __forceinline__ unsigned smem_u32(const void* p) {
    return (unsigned)__cvta_generic_to_shared(p);
}
__device__ __forceinline__ unsigned mapa_rank(unsigned a, unsigned r) {
    unsigned o; asm("mapa.shared::cluster.u32 %0,%1,%2;" : "=r"(o) : "r"(a), "r"(r));
    return o;
}
__device__ __forceinline__ void st_cluster_f32(unsigned a, float v) {
    asm volatile("st.shared::cluster.f32 [%0],%1;" :: "r"(a), "f"(v) : "memory");
}
__device__ __forceinline__ void mbar_init(unsigned a, unsigned cnt) {
    asm volatile("mbarrier.init.shared.b64 [%0],%1;" :: "r"(a), "r"(cnt) : "memory");
}
__device__ __forceinline__ void mbar_inval(unsigned a) {
    asm volatile("mbarrier.inval.shared.b64 [%0];" :: "r"(a) : "memory");
}
__device__ __forceinline__ void mbar_arrive_cluster(unsigned mapa_addr) {
    asm volatile("mbarrier.arrive.release.cluster.shared::cluster.b64 _, [%0];"
                 :: "r"(mapa_addr) : "memory");
}
__device__ __forceinline__ void mbar_wait_parity(unsigned a, unsigned ph) {
    asm volatile(
        "{\n\t.reg .pred P;\n"
        "LAB%=:\n\t"
        "mbarrier.try_wait.parity.acquire.cluster.shared::cta.b64 P, [%0], %1;\n\t"
        "@!P bra LAB%=;\n\t}"
        :: "r"(a), "r"(ph) : "memory");
}
__device__ __forceinline__ void cluster_sync_asm() {
    asm volatile("barrier.cluster.arrive.aligned;" ::: "memory");
    asm volatile("barrier.cluster.wait.aligned;" ::: "memory");
}

// ---------------- Phase A (proven R5) ----------------------------------------
__global__ void phaseA(const float* __restrict__ x,
                       const float* __restrict__ Wf0, const float* __restrict__ bf0,
                       const float* __restrict__ Wb0, const float* __restrict__ bb0)
{
    if (blockIdx.x == 0 && threadIdx.x < 2) {
        g_cnt0[threadIdx.x] = 0u;
        g_cntzx[threadIdx.x] = 0u;
    }

    const int d     = blockIdx.x >> 7;
    const int chunk = blockIdx.x & 127;
    const float* __restrict__ W    = d ? Wb0 : Wf0;
    const float* __restrict__ bias = d ? bb0 : bf0;

    __shared__ float xs[4][DD];
    const int tid = threadIdx.x;
    for (int i = tid; i < 4 * DD; i += 256) {
        int t4 = i >> 7, k = i & 127;
        int s = chunk * 4 + t4;
        int t = d ? (TT - 1 - s) : s;
        xs[t4][k] = x[(size_t)BLAST * TT * DD + (size_t)t * DD + k];
    }
    __syncthreads();

    float acc[4][4];
    #pragma unroll
    for (int j = 0; j < 4; j++) {
        float b = bias[tid + j * 256];
        #pragma unroll
        for (int t4 = 0; t4 < 4; t4++) acc[j][t4] = b;
    }
    #pragma unroll 4
    for (int k = 0; k < DD; k++) {
        float xv[4];
        #pragma unroll
        for (int t4 = 0; t4 < 4; t4++) xv[t4] = xs[t4][k];
        #pragma unroll
        for (int j = 0; j < 4; j++) {
            float w = W[k * 1024 + tid + j * 256];
            #pragma unroll
            for (int t4 = 0; t4 < 4; t4++) acc[j][t4] += xv[t4] * w;
        }
    }
    #pragma unroll
    for (int j = 0; j < 4; j++)
        #pragma unroll
        for (int t4 = 0; t4 < 4; t4++)
            g_zx0[d][chunk * 4 + t4][tid + j * 256] = acc[j][t4];
}

// ---------------- Phase B ----------------------------------------------------
// grid 64 x 256 threads, cluster (8,1,1).
//   bid 0..31 : engines. eng = bid>>3 (0:L0fw 1:L0bw 2:L1fw 3:L1bw), c = bid&7.
//   bid 32..63: helpers. d = (bid-32)>>4, hc = (bid-32)&15, 64 cols each.
__global__ void __launch_bounds__(256, 1) phaseB(
    const float* __restrict__ fw_state, const float* __restrict__ bw_state,
    const float* __restrict__ Wf0,
    const float* __restrict__ Wf1, const float* __restrict__ bf1,
    const float* __restrict__ Wb0,
    const float* __restrict__ Wb1, const float* __restrict__ bb1)
{
    __shared__ __align__(16) float hbuf[2][HD];   // engine: h double buffer (DSMEM tgt)
    __shared__ float redb[2][HD];                 // engine: partial sums (double buf)
    __shared__ float zbuf[2][128];                // engine: prefetched zx (double buf)
    __shared__ float cs[32];
    __shared__ __align__(8) unsigned long long mbar;

    const int bid = blockIdx.x;
    const int tid = threadIdx.x;

    if (bid < 32) {
        // ======================= cluster engine =============================
        const int eng = bid >> 3, c = bid & 7;
        const int layer = eng >> 1, d = eng & 1;
        const float* __restrict__ state = d ? bw_state : fw_state;
        const float* __restrict__ W = layer ? (d ? Wb1 : Wf1) : (d ? Wb0 : Wf0);
        const int rowbase = layer ? 256 : 128;   // recurrent rows of W

        const int p = tid >> 7;            // K half (128 rows)
        const int l = tid & 127;           // local col 0..127
        const int g = l >> 5, j = l & 31;
        const int gcol = g * 256 + c * 32 + j;

        float w[128];                      // recurrent weights, registers
        #pragma unroll
        for (int i = 0; i < 128; i++)
            w[i] = W[(size_t)(rowbase + p * 128 + i) * 1024 + gcol];

        const float* srow = state + (size_t)BLAST * 1024 + layer * 512;
        hbuf[0][tid] = srow[256 + tid];    // h_init, read by step 0
        if (tid < 32) cs[tid] = srow[c * 32 + tid];

        const float* zxs = layer ? &g_zx1[d][0][0] : &g_zx0[d][0][0];
        float*       hgl = layer ? &g_h1[d][0][0]  : &g_h0[d][0][0];
        unsigned* cnt0d  = &g_cnt0[d];
        unsigned* cntzxd = &g_cntzx[d];

        // gate warp: precompute remote addresses
        unsigned rs[2][8], rm[8];
        if (tid < 32) {
            #pragma unroll
            for (int b = 0; b < 2; b++) {
                unsigned a = smem_u32(&hbuf[b][c * 32 + tid]);
                #pragma unroll
                for (int r = 0; r < 8; r++) rs[b][r] = mapa_rank(a, (unsigned)r);
            }
            unsigned ma = smem_u32(&mbar);
            #pragma unroll
            for (int r = 0; r < 8; r++) rm[r] = mapa_rank(ma, (unsigned)r);
        }
        // fetch warp (tid 32..63): preload zbuf[0] = zx[step 0]
        if (tid >= 32 && tid < 64) {
            const int ft = tid - 32;
            if (layer == 1) {
                if (ft == 0) { while (acq_ld(cntzxd) < 16u) { } }
                __syncwarp();
            }
            #pragma unroll
            for (int gg = 0; gg < 4; gg++)
                zbuf[0][gg * 32 + ft] = __ldcg(zxs + 0 * 1024 + gg * 256 + c * 32 + ft);
        }
        if (tid == 0) mbar_init(smem_u32(&mbar), 256u);
        __syncthreads();
        cluster_sync_asm();    // peers' mbar/hbuf init visible before any arrive

        const unsigned mwait = smem_u32(&mbar);
        for (int s = 0; s < TT; s++) {
            const int sb = s & 1;
            if (s > 0) mbar_wait_parity(mwait, (unsigned)((s + 1) & 1));

            // dot over K half
            float acc = 0.0f;
            const float* hv = &hbuf[sb][p * 128];
            #pragma unroll
            for (int i = 0; i < 128; i += 4) {
                float4 h4 = *(const float4*)&hv[i];
                acc += w[i] * h4.x; acc += w[i + 1] * h4.y;
                acc += w[i + 2] * h4.z; acc += w[i + 3] * h4.w;
            }
            redb[sb][p * 128 + l] = acc;
            __syncthreads();               // dot complete CTA-wide

            if (tid < 32) {
                // gate warp
                float z[4];
                #pragma unroll
                for (int gg = 0; gg < 4; gg++)
                    z[gg] = redb[sb][gg * 32 + tid] + redb[sb][128 + gg * 32 + tid]
                          + zbuf[sb][gg * 32 + tid];
                float cn = fsig(z[2] + 1.0f) * cs[tid] + fsig(z[0]) * ftanh(z[1]);
                float hn = fsig(z[3]) * ftanh(cn);
                cs[tid] = cn;

                const int wb = (s + 1) & 1;
                #pragma unroll
                for (int r = 0; r < 8; r++) st_cluster_f32(rs[wb][r], hn);
                #pragma unroll
                for (int r = 0; r < 8; r++) mbar_arrive_cluster(rm[r]);

                __stcg(hgl + (size_t)s * HD + c * 32 + tid, hn);
                if (layer == 0) {
                    __syncwarp();
                    if (tid == 0) rel_add(cnt0d);
                }
            } else if (tid < 64) {
                // fetch warp: prefetch zx for step s+1
                if (s + 1 < TT) {
                    const int ft = tid - 32;
                    if (layer == 1) {
                        if (ft == 0) {
                            unsigned tgt = 16u * (unsigned)(s + 2);
                            while (acq_ld(cntzxd) < tgt) { }
                        }
                        __syncwarp();
                    }
                    #pragma unroll
                    for (int gg = 0; gg < 4; gg++)
                        zbuf[(s + 1) & 1][gg * 32 + ft] =
                            __ldcg(zxs + (size_t)(s + 1) * 1024 + gg * 256 + c * 32 + ft);
                }
            }
        }
        cluster_sync_asm();    // keep SMEM alive for in-flight peer stores
        if (tid == 0) mbar_inval(smem_u32(&mbar));
    } else {
        // ======================= helper CTAs (proven sync) ==================
        const int hix = bid - 32;
        const int d   = hix >> 4;
        const int hc  = hix & 15;
        const float* __restrict__ W    = d ? Wb1 : Wf1;
        const float* __restrict__ bias = d ? bb1 : bf1;
        const int p = tid >> 6;            // K quarter (64 rows of W1[0:256])
        const int l = tid & 63;            // col (64 per CTA)
        const int col = hc * 64 + l;

        float w[64];
        #pragma unroll
        for (int i = 0; i < 64; i++)
            w[i] = W[(size_t)(p * 64 + i) * 1024 + col];
        const float bb = (tid < 64) ? bias[hc * 64 + tid] : 0.0f;

        float* hs  = &hbuf[0][0];          // reuse engine smem
        float* red = &redb[0][0];
        unsigned* cnt0d  = &g_cnt0[d];
        unsigned* cntzxd = &g_cntzx[d];
        const int koff = p * 64;

        for (int s = 0; s < TT; s++) {
            if (tid == 0) {
                unsigned tgt = 8u * (unsigned)(s + 1);   // 8 L0 CTAs per dir
                while (acq_ld(cnt0d) < tgt) { }
            }
            __syncthreads();
            hs[tid] = __ldcg(&g_h0[d][s][tid]);
            __syncthreads();

            float acc = 0.0f;
            #pragma unroll
            for (int i = 0; i < 64; i += 4) {
                float4 h4 = *(const float4*)&hs[koff + i];
                acc += w[i] * h4.x; acc += w[i + 1] * h4.y;
                acc += w[i + 2] * h4.z; acc += w[i + 3] * h4.w;
            }
            red[tid] = acc;
            __syncthreads();
            if (tid < 64) {
                float z = bb + red[tid] + red[64 + tid] + red[128 + tid] + red[192 + tid];
                __stcg(&g_zx1[d][s][hc * 64 + tid], z);
            }
            __syncthreads();               // all 64 stores issued before signal
            if (tid == 0) rel_add(cntzxd);
        }
    }
}

// ---------------- Phase C: final dense ---------------------------------------
__global__ void phaseC(const float* __restrict__ Wd, const float* __restrict__ bd,
                       float* __restrict__ out)
{
    const int chunk = blockIdx.x;
    const int o = threadIdx.x;
    __shared__ float hsm[8][512];
    for (int i = threadIdx.x; i < 8 * 512; i += 128) {
        int t8 = i >> 9, k = i & 511;
        int t = chunk * 8 + t8;
        hsm[t8][k] = (k < 256) ? g_h1[0][t][k] : g_h1[1][TT - 1 - t][k - 256];
    }
    __syncthreads();
    float b = bd[o];
    float acc[8];
    #pragma unroll
    for (int t8 = 0; t8 < 8; t8++) acc[t8] = b;
    #pragma unroll 8
    for (int k = 0; k < 512; k++) {
        float w = Wd[k * 128 + o];
        #pragma unroll
        for (int t8 = 0; t8 < 8; t8++) acc[t8] += hsm[t8][k] * w;
    }
    #pragma unroll
    for (int t8 = 0; t8 < 8; t8++) out[(chunk * 8 + t8) * 128 + o] = acc[t8];
}

// ---------------- launch -----------------------------------------------------
extern "C" void kernel_launch(void* const* d_in, const int* in_sizes, int n_in,
                              void* d_out, int out_size)
{
    (void)in_sizes; (void)n_in; (void)out_size;
    const float* x        = (const float*)d_in[0];
    const float* fw_state = (const float*)d_in[1];
    const float* bw_state = (const float*)d_in[2];
    const float* Wf0 = (const float*)d_in[3];
    const float* bf0 = (const float*)d_in[4];
    const float* Wf1 = (const float*)d_in[5];
    const float* bf1 = (const float*)d_in[6];
    const float* Wb0 = (const float*)d_in[7];
    const float* bb0 = (const float*)d_in[8];
    const float* Wb1 = (const float*)d_in[9];
    const float* bb1 = (const float*)d_in[10];
    const float* Wd  = (const float*)d_in[11];
    const float* bd  = (const float*)d_in[12];

    phaseA<<<256, 256>>>(x, Wf0, bf0, Wb0, bb0);

    cudaLaunchConfig_t cfg = {};
    cfg.gridDim  = dim3(64, 1, 1);
    cfg.blockDim = dim3(256, 1, 1);
    cfg.dynamicSmemBytes = 0;
    cfg.stream = 0;
    cudaLaunchAttribute attr[1];
    attr[0].id = cudaLaunchAttributeClusterDimension;
    attr[0].val.clusterDim.x = 8;
    attr[0].val.clusterDim.y = 1;
    attr[0].val.clusterDim.z = 1;
    cfg.attrs = attr;
    cfg.numAttrs = 1;
    cudaLaunchKernelEx(&cfg, phaseB, fw_state, bw_state,
                       Wf0, Wf1, bf1, Wb0, Wb1, bb1);

    phaseC<<<64, 128>>>(Wd, bd, (float*)d_out);
}

// round 7
// speedup vs baseline: 1.6541x; 1.6541x over previous
#include <cuda_runtime.h>
#include <cstddef>
#include <cstdint>

// Bidirectional 2-layer LSTM; only batch row 255 feeds the output (B -> 1).
// Round 7: R6's correct 8-CTA cluster engines (DSMEM h push) with the signal
// path swapped from per-lane mbarrier arrives (256 serialized RMWs/step) to the
// PROVEN L2 counter (1 red.release per CTA per step, acquire-load polling).

#define TT 512
#define HD 256
#define DD 128
#define BLAST 255

// ---------------- scratch (static device memory) ----------------------------
__device__ float g_zx0[2][TT][1024];   // layer0 x-part + bias (phaseA)
__device__ float g_zx1[2][TT][1024];   // layer1 x-part + bias (helpers)
__device__ float g_h0[2][TT][HD];      // layer0 h (published for helpers)
__device__ float g_h1[2][TT][HD];      // layer1 h (for phaseC)
__device__ unsigned g_csync[4];        // per-engine step counters (8 adds/step)
__device__ unsigned g_cntzx[2];        // helper zx1 counters (16 adds/step)

// fast saturating gate math (proven R5/R6)
__device__ __forceinline__ float fsig(float x) {
    return __fdividef(1.0f, 1.0f + __expf(-x));
}
__device__ __forceinline__ float ftanh(float x) {
    return 1.0f - __fdividef(2.0f, __expf(2.0f * x) + 1.0f);
}

// proven counter ops (R2/R5/R6)
__device__ __forceinline__ void rel_add(unsigned* p) {
    asm volatile("red.release.gpu.global.add.u32 [%0], 1;" :: "l"(p) : "memory");
}
__device__ __forceinline__ unsigned acq_ld(const unsigned* p) {
    unsigned v;
    asm volatile("ld.acquire.gpu.global.u32 %0, [%1];" : "=r"(v) : "l"(p) : "memory");
    return v;
}

// cluster primitives (proven R6)
__device__ __forceinline__ unsigned smem_u32(const void* p) {
    return (unsigned)__cvta_generic_to_shared(p);
}
__device__ __forceinline__ unsigned mapa_rank(unsigned a, unsigned r) {
    unsigned o; asm("mapa.shared::cluster.u32 %0,%1,%2;" : "=r"(o) : "r"(a), "r"(r));
    return o;
}
__device__ __forceinline__ void st_cluster_f32(unsigned a, float v) {
    asm volatile("st.shared::cluster.f32 [%0],%1;" :: "r"(a), "f"(v) : "memory");
}
__device__ __forceinline__ void cluster_sync_asm() {
    asm volatile("barrier.cluster.arrive.aligned;" ::: "memory");
    asm volatile("barrier.cluster.wait.aligned;" ::: "memory");
}

// ---------------- Phase A (proven R5/R6) -------------------------------------
__global__ void phaseA(const float* __restrict__ x,
                       const float* __restrict__ Wf0, const float* __restrict__ bf0,
                       const float* __restrict__ Wb0, const float* __restrict__ bb0)
{
    if (blockIdx.x == 0 && threadIdx.x < 6) {
        if (threadIdx.x < 4) g_csync[threadIdx.x] = 0u;
        else g_cntzx[threadIdx.x - 4] = 0u;
    }

    const int d     = blockIdx.x >> 7;
    const int chunk = blockIdx.x & 127;
    const float* __restrict__ W    = d ? Wb0 : Wf0;
    const float* __restrict__ bias = d ? bb0 : bf0;

    __shared__ float xs[4][DD];
    const int tid = threadIdx.x;
    for (int i = tid; i < 4 * DD; i += 256) {
        int t4 = i >> 7, k = i & 127;
        int s = chunk * 4 + t4;
        int t = d ? (TT - 1 - s) : s;
        xs[t4][k] = x[(size_t)BLAST * TT * DD + (size_t)t * DD + k];
    }
    __syncthreads();

    float acc[4][4];
    #pragma unroll
    for (int j = 0; j < 4; j++) {
        float b = bias[tid + j * 256];
        #pragma unroll
        for (int t4 = 0; t4 < 4; t4++) acc[j][t4] = b;
    }
    #pragma unroll 4
    for (int k = 0; k < DD; k++) {
        float xv[4];
        #pragma unroll
        for (int t4 = 0; t4 < 4; t4++) xv[t4] = xs[t4][k];
        #pragma unroll
        for (int j = 0; j < 4; j++) {
            float w = W[k * 1024 + tid + j * 256];
            #pragma unroll
            for (int t4 = 0; t4 < 4; t4++) acc[j][t4] += xv[t4] * w;
        }
    }
    #pragma unroll
    for (int j = 0; j < 4; j++)
        #pragma unroll
        for (int t4 = 0; t4 < 4; t4++)
            g_zx0[d][chunk * 4 + t4][tid + j * 256] = acc[j][t4];
}

// ---------------- Phase B ----------------------------------------------------
// grid 64 x 256 threads, cluster (8,1,1).
//   bid 0..31 : engines. eng = bid>>3 (0:L0fw 1:L0bw 2:L1fw 3:L1bw), c = bid&7.
//   bid 32..63: helpers. d = (bid-32)>>4, hc = (bid-32)&15, 64 cols each.
__global__ void __launch_bounds__(256, 1) phaseB(
    const float* __restrict__ fw_state, const float* __restrict__ bw_state,
    const float* __restrict__ Wf0,
    const float* __restrict__ Wf1, const float* __restrict__ bf1,
    const float* __restrict__ Wb0,
    const float* __restrict__ Wb1, const float* __restrict__ bb1)
{
    __shared__ __align__(16) float hbuf[2][HD];   // h double buffer (DSMEM target)
    __shared__ float redb[2][HD];                 // partial sums (double buffer)
    __shared__ float zbuf[2][128];                // prefetched zx (double buffer)
    __shared__ float cs[32];

    const int bid = blockIdx.x;
    const int tid = threadIdx.x;

    if (bid < 32) {
        // ======================= cluster engine =============================
        const int eng = bid >> 3, c = bid & 7;
        const int layer = eng >> 1, d = eng & 1;
        const float* __restrict__ state = d ? bw_state : fw_state;
        const float* __restrict__ W = layer ? (d ? Wb1 : Wf1) : (d ? Wb0 : Wf0);
        const int rowbase = layer ? 256 : 128;   // recurrent rows of W

        const int p = tid >> 7;            // K half (128 rows)
        const int l = tid & 127;           // local col 0..127
        const int g = l >> 5, j = l & 31;
        const int gcol = g * 256 + c * 32 + j;

        float w[128];                      // recurrent weights, registers
        #pragma unroll
        for (int i = 0; i < 128; i++)
            w[i] = W[(size_t)(rowbase + p * 128 + i) * 1024 + gcol];

        const float* srow = state + (size_t)BLAST * 1024 + layer * 512;
        hbuf[0][tid] = srow[256 + tid];    // h_init, consumed at step 0
        if (tid < 32) cs[tid] = srow[c * 32 + tid];

        const float* zxs = layer ? &g_zx1[d][0][0] : &g_zx0[d][0][0];
        float*       hgl = layer ? &g_h1[d][0][0]  : &g_h0[d][0][0];
        unsigned* cnt    = &g_csync[eng];
        unsigned* cntzxd = &g_cntzx[d];

        // gate warp: precompute remote hbuf addresses (both buffers x 8 ranks)
        unsigned rs[2][8];
        if (tid < 32) {
            #pragma unroll
            for (int b = 0; b < 2; b++) {
                unsigned a = smem_u32(&hbuf[b][c * 32 + tid]);
                #pragma unroll
                for (int r = 0; r < 8; r++) rs[b][r] = mapa_rank(a, (unsigned)r);
            }
        }
        // fetch warp (tid 32..63): preload zbuf[0] = zx[step 0]
        if (tid >= 32 && tid < 64) {
            const int ft = tid - 32;
            if (layer == 1) {
                if (ft == 0) { while (acq_ld(cntzxd) < 16u) { } }
                __syncwarp();
            }
            #pragma unroll
            for (int gg = 0; gg < 4; gg++)
                zbuf[0][gg * 32 + ft] = __ldcg(zxs + 0 * 1024 + gg * 256 + c * 32 + ft);
        }
        __syncthreads();
        cluster_sync_asm();    // all peers resident + hbuf[0] initialized

        for (int s = 0; s < TT; s++) {
            const int sb = s & 1;
            if (s > 0) {
                if (tid == 0) {
                    unsigned tgt = 8u * (unsigned)s;      // all 8 stored h[s-1]
                    while (acq_ld(cnt) < tgt) { }
                }
                __syncthreads();
            }

            // dot over K half (h[s-1] already local via DSMEM push)
            float acc = 0.0f;
            const float* hv = &hbuf[sb][p * 128];
            #pragma unroll
            for (int i = 0; i < 128; i += 4) {
                float4 h4 = *(const float4*)&hv[i];
                acc += w[i] * h4.x; acc += w[i + 1] * h4.y;
                acc += w[i + 2] * h4.z; acc += w[i + 3] * h4.w;
            }
            redb[sb][p * 128 + l] = acc;
            __syncthreads();               // dot complete CTA-wide

            if (tid < 32) {
                // gate warp
                float z[4];
                #pragma unroll
                for (int gg = 0; gg < 4; gg++)
                    z[gg] = redb[sb][gg * 32 + tid] + redb[sb][128 + gg * 32 + tid]
                          + zbuf[sb][gg * 32 + tid];
                float cn = fsig(z[2] + 1.0f) * cs[tid] + fsig(z[0]) * ftanh(z[1]);
                float hn = fsig(z[3]) * ftanh(cn);
                cs[tid] = cn;

                // push h[s] into all 8 peers' other buffer (incl. self)
                const int wb = (s + 1) & 1;
                #pragma unroll
                for (int r = 0; r < 8; r++) st_cluster_f32(rs[wb][r], hn);
                // publish to L2 (helpers for L0; phaseC for L1)
                __stcg(hgl + (size_t)s * HD + c * 32 + tid, hn);
                __syncwarp();
                if (tid == 0) rel_add(cnt);   // one signal per CTA per step
            } else if (tid < 64) {
                // fetch warp: prefetch zx for step s+1
                if (s + 1 < TT) {
                    const int ft = tid - 32;
                    if (layer == 1) {
                        if (ft == 0) {
                            unsigned tgt = 16u * (unsigned)(s + 2);
                            while (acq_ld(cntzxd) < tgt) { }
                        }
                        __syncwarp();
                    }
                    #pragma unroll
                    for (int gg = 0; gg < 4; gg++)
                        zbuf[(s + 1) & 1][gg * 32 + ft] =
                            __ldcg(zxs + (size_t)(s + 1) * 1024 + gg * 256 + c * 32 + ft);
                }
            }
        }
        cluster_sync_asm();    // keep SMEM alive for in-flight peer stores
    } else {
        // ======================= helper CTAs (proven sync) ==================
        const int hix = bid - 32;
        const int d   = hix >> 4;
        const int hc  = hix & 15;
        const float* __restrict__ W    = d ? Wb1 : Wf1;
        const float* __restrict__ bias = d ? bb1 : bf1;
        const int p = tid >> 6;            // K quarter (64 rows of W1[0:256])
        const int l = tid & 63;            // col (64 per CTA)
        const int col = hc * 64 + l;

        float w[64];
        #pragma unroll
        for (int i = 0; i < 64; i++)
            w[i] = W[(size_t)(p * 64 + i) * 1024 + col];
        const float bb = (tid < 64) ? bias[hc * 64 + tid] : 0.0f;

        float* hs  = &hbuf[0][0];          // reuse engine smem
        float* red = &redb[0][0];
        unsigned* cnt0d  = &g_csync[d];    // L0 engine counter for this dir
        unsigned* cntzxd = &g_cntzx[d];
        const int koff = p * 64;

        for (int s = 0; s < TT; s++) {
            if (tid == 0) {
                unsigned tgt = 8u * (unsigned)(s + 1);   // 8 L0 CTAs per dir
                while (acq_ld(cnt0d) < tgt) { }
            }
            __syncthreads();
            hs[tid] = __ldcg(&g_h0[d][s][tid]);
            __syncthreads();

            float acc = 0.0f;
            #pragma unroll
            for (int i = 0; i < 64; i += 4) {
                float4 h4 = *(const float4*)&hs[koff + i];
                acc += w[i] * h4.x; acc += w[i + 1] * h4.y;
                acc += w[i + 2] * h4.z; acc += w[i + 3] * h4.w;
            }
            red[tid] = acc;
            __syncthreads();
            if (tid < 64) {
                float z = bb + red[tid] + red[64 + tid] + red[128 + tid] + red[192 + tid];
                __stcg(&g_zx1[d][s][hc * 64 + tid], z);
            }
            __syncthreads();               // all 64 stores issued before signal
            if (tid == 0) rel_add(cntzxd);
        }
    }
}

// ---------------- Phase C: final dense ---------------------------------------
__global__ void phaseC(const float* __restrict__ Wd, const float* __restrict__ bd,
                       float* __restrict__ out)
{
    const int chunk = blockIdx.x;
    const int o = threadIdx.x;
    __shared__ float hsm[8][512];
    for (int i = threadIdx.x; i < 8 * 512; i += 128) {
        int t8 = i >> 9, k = i & 511;
        int t = chunk * 8 + t8;
        hsm[t8][k] = (k < 256) ? g_h1[0][t][k] : g_h1[1][TT - 1 - t][k - 256];
    }
    __syncthreads();
    float b = bd[o];
    float acc[8];
    #pragma unroll
    for (int t8 = 0; t8 < 8; t8++) acc[t8] = b;
    #pragma unroll 8
    for (int k = 0; k < 512; k++) {
        float w = Wd[k * 128 + o];
        #pragma unroll
        for (int t8 = 0; t8 < 8; t8++) acc[t8] += hsm[t8][k] * w;
    }
    #pragma unroll
    for (int t8 = 0; t8 < 8; t8++) out[(chunk * 8 + t8) * 128 + o] = acc[t8];
}

// ---------------- launch -----------------------------------------------------
extern "C" void kernel_launch(void* const* d_in, const int* in_sizes, int n_in,
                              void* d_out, int out_size)
{
    (void)in_sizes; (void)n_in; (void)out_size;
    const float* x        = (const float*)d_in[0];
    const float* fw_state = (const float*)d_in[1];
    const float* bw_state = (const float*)d_in[2];
    const float* Wf0 = (const float*)d_in[3];
    const float* bf0 = (const float*)d_in[4];
    const float* Wf1 = (const float*)d_in[5];
    const float* bf1 = (const float*)d_in[6];
    const float* Wb0 = (const float*)d_in[7];
    const float* bb0 = (const float*)d_in[8];
    const float* Wb1 = (const float*)d_in[9];
    const float* bb1 = (const float*)d_in[10];
    const float* Wd  = (const float*)d_in[11];
    const float* bd  = (const float*)d_in[12];

    phaseA<<<256, 256>>>(x, Wf0, bf0, Wb0, bb0);

    cudaLaunchConfig_t cfg = {};
    cfg.gridDim  = dim3(64, 1, 1);
    cfg.blockDim = dim3(256, 1, 1);
    cfg.dynamicSmemBytes = 0;
    cfg.stream = 0;
    cudaLaunchAttribute attr[1];
    attr[0].id = cudaLaunchAttributeClusterDimension;
    attr[0].val.clusterDim.x = 8;
    attr[0].val.clusterDim.y = 1;
    attr[0].val.clusterDim.z = 1;
    cfg.attrs = attr;
    cfg.numAttrs = 1;
    cudaLaunchKernelEx(&cfg, phaseB, fw_state, bw_state,
                       Wf0, Wf1, bf1, Wb0, Wb1, bb1);

    phaseC<<<64, 128>>>(Wd, bd, (float*)d_out);
}